// round 1
// baseline (speedup 1.0000x reference)
#include <cuda_runtime.h>
#include <math.h>

#define B_  8
#define C_  64
#define NN  2304      // 48*48
#define NT  36        // NN / 64

// scratch (static device globals; no runtime allocation)
__device__ float g_q[B_ * C_ * NN];        // normalized q, [B][C][N]
__device__ float g_rowsum[B_ * NN];        // softmax denominators

// ---------- packed f32x2 helpers (FFMA2) ----------
static __device__ __forceinline__ unsigned long long pack2(float x, float y) {
    unsigned long long r;
    asm("mov.b64 %0, {%1, %2};" : "=l"(r) : "f"(x), "f"(y));
    return r;
}
static __device__ __forceinline__ void unpack2(unsigned long long v, float& x, float& y) {
    asm("mov.b64 {%0, %1}, %2;" : "=f"(x), "=f"(y) : "l"(v));
}
static __device__ __forceinline__ void ffma2(unsigned long long& acc,
                                             unsigned long long a,
                                             unsigned long long b) {
    asm("fma.rn.f32x2 %0, %1, %2, %0;" : "+l"(acc) : "l"(a), "l"(b));
}

// ---------- K1: q = l2normalize(x + gamma*pos) over channel axis ----------
__global__ __launch_bounds__(256) void qnorm_kernel(const float* __restrict__ x,
                                                    const float* __restrict__ pos,
                                                    const float* __restrict__ gamma_p) {
    int idx = blockIdx.x * blockDim.x + threadIdx.x;   // over B*N
    if (idx >= B_ * NN) return;
    int b = idx / NN;
    int n = idx - b * NN;
    float gamma = *gamma_p;
    const float* xb = x   + (size_t)b * C_ * NN + n;
    const float* pb = pos + (size_t)b * C_ * NN + n;
    float vals[C_];
    float s = 0.f;
#pragma unroll
    for (int c = 0; c < C_; c++) {
        float val = xb[(size_t)c * NN] + gamma * pb[(size_t)c * NN];
        vals[c] = val;
        s += val * val;
    }
    float inv = 1.0f / sqrtf(s + 1e-6f);
    float* qb = g_q + (size_t)b * C_ * NN + n;
#pragma unroll
    for (int c = 0; c < C_; c++) qb[(size_t)c * NN] = vals[c] * inv;
}

// ---------- K2: E = exp(bg*(Qn^T Qm) - |bg|) -> beta region; rowsums ----------
// grid (NT, B), 256 threads; block handles 64 n-rows x all m.
__global__ __launch_bounds__(256) void scores_kernel(float* __restrict__ beta_out,
                                                     const float* __restrict__ bg_p) {
    __shared__ float Qn[C_][64];   // [c][n]
    __shared__ float Qm[C_][64];   // [c][m]

    int b  = blockIdx.y;
    int n0 = blockIdx.x * 64;
    int tid = threadIdx.x;
    int tx = tid & 15;         // m sub-tile (cols)
    int ty = tid >> 4;         // n sub-tile (rows)

    float bg    = *bg_p;
    float shift = fabsf(bg);

    const float* qb = g_q + (size_t)b * C_ * NN;

    // load Qn tile: rows c (64) x 64 n, coalesced, no transpose needed (k = c is slow dim)
    {
        int c   = tid >> 2;
        int f40 = (tid & 3) * 4;                       // float4 index base
        const float4* src = reinterpret_cast<const float4*>(qb + (size_t)c * NN + n0);
        float4*       dst = reinterpret_cast<float4*>(&Qn[c][0]);
#pragma unroll
        for (int k = 0; k < 4; k++) dst[f40 + k] = src[f40 + k];
    }

    float rsum[4] = {0.f, 0.f, 0.f, 0.f};
    float* betab = beta_out + (size_t)b * NN * NN;

    for (int mt = 0; mt < NT; mt++) {
        int m0 = mt * 64;
        __syncthreads();
        {
            int c   = tid >> 2;
            int f40 = (tid & 3) * 4;
            const float4* src = reinterpret_cast<const float4*>(qb + (size_t)c * NN + m0);
            float4*       dst = reinterpret_cast<float4*>(&Qm[c][0]);
#pragma unroll
            for (int k = 0; k < 4; k++) dst[f40 + k] = src[f40 + k];
        }
        __syncthreads();

        unsigned long long acc2[4][2] = {0ULL, 0ULL, 0ULL, 0ULL, 0ULL, 0ULL, 0ULL, 0ULL};
#pragma unroll 16
        for (int c = 0; c < C_; c++) {
            float4 a4 = *reinterpret_cast<const float4*>(&Qn[c][ty * 4]);
            const unsigned long long* bp =
                reinterpret_cast<const unsigned long long*>(&Qm[c][tx * 4]);
            unsigned long long b0 = bp[0], b1 = bp[1];
            unsigned long long ab;
            ab = pack2(a4.x, a4.x); ffma2(acc2[0][0], ab, b0); ffma2(acc2[0][1], ab, b1);
            ab = pack2(a4.y, a4.y); ffma2(acc2[1][0], ab, b0); ffma2(acc2[1][1], ab, b1);
            ab = pack2(a4.z, a4.z); ffma2(acc2[2][0], ab, b0); ffma2(acc2[2][1], ab, b1);
            ab = pack2(a4.w, a4.w); ffma2(acc2[3][0], ab, b0); ffma2(acc2[3][1], ab, b1);
        }

        // exp + store unnormalized E + accumulate rowsums
#pragma unroll
        for (int i = 0; i < 4; i++) {
            float s0, s1, s2, s3;
            unpack2(acc2[i][0], s0, s1);
            unpack2(acc2[i][1], s2, s3);
            float e0 = __expf(fmaf(s0, bg, -shift));
            float e1 = __expf(fmaf(s1, bg, -shift));
            float e2 = __expf(fmaf(s2, bg, -shift));
            float e3 = __expf(fmaf(s3, bg, -shift));
            rsum[i] += (e0 + e1) + (e2 + e3);
            float4 ev = make_float4(e0, e1, e2, e3);
            *reinterpret_cast<float4*>(betab + (size_t)(n0 + ty * 4 + i) * NN + m0 + tx * 4) = ev;
        }
    }

    // reduce rowsums across tx (16 lanes within each half-warp group)
#pragma unroll
    for (int i = 0; i < 4; i++) {
        float s = rsum[i];
#pragma unroll
        for (int off = 8; off >= 1; off >>= 1)
            s += __shfl_xor_sync(0xffffffffu, s, off);
        if (tx == 0) g_rowsum[b * NN + n0 + ty * 4 + i] = s;
    }
}

// ---------- K3: normalize beta in place + O = V * beta^T + gated combine ----------
// grid (NT, B), 256 threads; block handles n-rows [n0, n0+64) x all 64 c.
__global__ __launch_bounds__(256) void out_kernel(float* __restrict__ beta_out,
                                                  float* __restrict__ out,
                                                  const float* __restrict__ v,
                                                  const float* __restrict__ sg0_p,
                                                  const float* __restrict__ sg1_p) {
    __shared__ float Bs[64][64];   // [m][n]  (transposed for outer product)
    __shared__ float Vs[64][64];   // [m][c]
    __shared__ float invs[64];

    int b  = blockIdx.y;
    int n0 = blockIdx.x * 64;
    int tid = threadIdx.x;
    int tx = tid & 15;     // c sub-tile
    int ty = tid >> 4;     // n sub-tile

    if (tid < 64) invs[tid] = 1.0f / g_rowsum[b * NN + n0 + tid];
    __syncthreads();

    unsigned long long acc2[4][2] = {0ULL, 0ULL, 0ULL, 0ULL, 0ULL, 0ULL, 0ULL, 0ULL};

    float*       betab = beta_out + (size_t)b * NN * NN;
    const float* vb    = v + (size_t)b * C_ * NN;

    for (int mt = 0; mt < NT; mt++) {
        int m0 = mt * 64;
        __syncthreads();
        {
            int row = tid >> 2;              // n for E tile, c for V tile
            int f40 = (tid & 3) * 4;
            float inv = invs[row];
            float* grow = betab + (size_t)(n0 + row) * NN + m0;
#pragma unroll
            for (int k = 0; k < 4; k++) {
                float4 e = reinterpret_cast<float4*>(grow)[f40 + k];
                e.x *= inv; e.y *= inv; e.z *= inv; e.w *= inv;
                reinterpret_cast<float4*>(grow)[f40 + k] = e;   // normalized beta out
                int m = (f40 + k) * 4;
                Bs[m + 0][row] = e.x; Bs[m + 1][row] = e.y;
                Bs[m + 2][row] = e.z; Bs[m + 3][row] = e.w;
            }
            const float* vrow = vb + (size_t)row * NN + m0;
#pragma unroll
            for (int k = 0; k < 4; k++) {
                float4 e = reinterpret_cast<const float4*>(vrow)[f40 + k];
                int m = (f40 + k) * 4;
                Vs[m + 0][row] = e.x; Vs[m + 1][row] = e.y;
                Vs[m + 2][row] = e.z; Vs[m + 3][row] = e.w;
            }
        }
        __syncthreads();

#pragma unroll 16
        for (int m = 0; m < 64; m++) {
            float4 a4 = *reinterpret_cast<const float4*>(&Bs[m][ty * 4]);  // n dim
            const unsigned long long* bp =
                reinterpret_cast<const unsigned long long*>(&Vs[m][tx * 4]); // c dim
            unsigned long long b0 = bp[0], b1 = bp[1];
            unsigned long long ab;
            ab = pack2(a4.x, a4.x); ffma2(acc2[0][0], ab, b0); ffma2(acc2[0][1], ab, b1);
            ab = pack2(a4.y, a4.y); ffma2(acc2[1][0], ab, b0); ffma2(acc2[1][1], ab, b1);
            ab = pack2(a4.z, a4.z); ffma2(acc2[2][0], ab, b0); ffma2(acc2[2][1], ab, b1);
            ab = pack2(a4.w, a4.w); ffma2(acc2[3][0], ab, b0); ffma2(acc2[3][1], ab, b1);
        }
    }

    // epilogue: out = w0 * o + w1 * v   (o[n][c] in acc)
    float eg0 = __expf(*sg0_p);
    float eg1 = __expf(*sg1_p);
    float tot = eg0 + eg1;
    float w0 = eg0 / tot, w1 = eg1 / tot;

    float oacc[4][4];
#pragma unroll
    for (int i = 0; i < 4; i++) {
        unpack2(acc2[i][0], oacc[i][0], oacc[i][1]);
        unpack2(acc2[i][1], oacc[i][2], oacc[i][3]);
    }

    float* ob = out + (size_t)b * C_ * NN;
#pragma unroll
    for (int j = 0; j < 4; j++) {
        int c = tx * 4 + j;
        const float4 vv = *reinterpret_cast<const float4*>(vb + (size_t)c * NN + n0 + ty * 4);
        float4 r;
        r.x = w0 * oacc[0][j] + w1 * vv.x;
        r.y = w0 * oacc[1][j] + w1 * vv.y;
        r.z = w0 * oacc[2][j] + w1 * vv.z;
        r.w = w0 * oacc[3][j] + w1 * vv.w;
        *reinterpret_cast<float4*>(ob + (size_t)c * NN + n0 + ty * 4) = r;
    }
}

// ---------- launch ----------
extern "C" void kernel_launch(void* const* d_in, const int* in_sizes, int n_in,
                              void* d_out, int out_size) {
    const float* x     = (const float*)d_in[0];
    const float* v     = (const float*)d_in[1];
    const float* pos   = (const float*)d_in[2];
    const float* gamma = (const float*)d_in[3];
    const float* bg    = (const float*)d_in[4];
    const float* sg0   = (const float*)d_in[5];
    const float* sg1   = (const float*)d_in[6];

    float* out  = (float*)d_out;
    float* beta = out + (size_t)B_ * C_ * NN;   // [out | beta] concatenation

    qnorm_kernel<<<(B_ * NN + 255) / 256, 256>>>(x, pos, gamma);

    dim3 grid(NT, B_);
    scores_kernel<<<grid, 256>>>(beta, bg);
    out_kernel<<<grid, 256>>>(beta, out, v, sg0, sg1);
}

// round 3
// speedup vs baseline: 2.0644x; 2.0644x over previous
#include <cuda_runtime.h>
#include <math.h>
#include <stdint.h>

#define B_   8
#define C_   64
#define NN   2304          // 48*48
#define NBLK 128           // n rows per CTA
#define MT   128           // m per tile
#define NT_M 18
#define NT_N 18

// ---------------- scratch ----------------
__device__ unsigned short g_qh[B_ * NN * C_];   // [b][n][c] bf16 hi
__device__ unsigned short g_ql[B_ * NN * C_];   // residual
__device__ unsigned short g_vh[B_ * C_ * NN];   // [b][c][m]
__device__ unsigned short g_vl[B_ * C_ * NN];
__device__ float          g_inv[B_ * NN];       // 1 / rowsum

// ---------------- helpers ----------------
static __device__ __forceinline__ uint32_t smem_u32(const void* p) {
    uint32_t a;
    asm("{ .reg .u64 t; cvta.to.shared.u64 t, %1; cvt.u32.u64 %0, t; }" : "=r"(a) : "l"(p));
    return a;
}
static __device__ __forceinline__ uint32_t swz(uint32_t o) { return o ^ ((o >> 3) & 0x70u); }

static __device__ __forceinline__ void ldsm4(uint32_t& r0, uint32_t& r1,
                                             uint32_t& r2, uint32_t& r3, uint32_t a) {
    asm volatile("ldmatrix.sync.aligned.m8n8.x4.shared.b16 {%0,%1,%2,%3}, [%4];"
                 : "=r"(r0), "=r"(r1), "=r"(r2), "=r"(r3) : "r"(a));
}
static __device__ __forceinline__ void mma_bf16(float (&d)[4], const uint32_t (&a)[4],
                                                uint32_t b0, uint32_t b1) {
    asm volatile(
        "mma.sync.aligned.m16n8k16.row.col.f32.bf16.bf16.f32 "
        "{%0,%1,%2,%3}, {%4,%5,%6,%7}, {%8,%9}, {%0,%1,%2,%3};"
        : "+f"(d[0]), "+f"(d[1]), "+f"(d[2]), "+f"(d[3])
        : "r"(a[0]), "r"(a[1]), "r"(a[2]), "r"(a[3]), "r"(b0), "r"(b1));
}
// pack two fp32 into bf16x2 by truncation (hi parts)
static __device__ __forceinline__ uint32_t hipack(float x, float y) {
    return __byte_perm(__float_as_uint(x), __float_as_uint(y), 0x7632);
}
static __device__ __forceinline__ uint32_t lopack(float x, float y) {
    float rx = x - __uint_as_float(__float_as_uint(x) & 0xFFFF0000u);
    float ry = y - __uint_as_float(__float_as_uint(y) & 0xFFFF0000u);
    uint32_t r;
    asm("cvt.rn.bf16x2.f32 %0, %1, %2;" : "=r"(r) : "f"(ry), "f"(rx));
    return r;
}

// ---------------- phase 1a: q split ----------------
__global__ __launch_bounds__(256) void qsplit_kernel(const float* __restrict__ x,
                                                     const float* __restrict__ pos,
                                                     const float* __restrict__ gamma_p) {
    int idx = blockIdx.x * blockDim.x + threadIdx.x;
    if (idx >= B_ * NN) return;
    int b = idx / NN, n = idx - b * NN;
    float gamma = *gamma_p;
    const float* xb = x   + (size_t)b * C_ * NN + n;
    const float* pb = pos + (size_t)b * C_ * NN + n;
    float q[C_]; float s = 0.f;
#pragma unroll
    for (int c = 0; c < C_; c++) {
        float v = xb[(size_t)c * NN] + gamma * pb[(size_t)c * NN];
        q[c] = v; s += v * v;
    }
    float inv = 1.0f / sqrtf(s + 1e-6f);
    uint32_t hp[32], lp[32];
#pragma unroll
    for (int i = 0; i < 32; i++) {
        float a = q[2 * i] * inv, bv = q[2 * i + 1] * inv;
        hp[i] = hipack(a, bv);
        lp[i] = lopack(a, bv);
    }
    uint4* ph = reinterpret_cast<uint4*>(reinterpret_cast<uint32_t*>(g_qh) + (size_t)idx * 32);
    uint4* pl = reinterpret_cast<uint4*>(reinterpret_cast<uint32_t*>(g_ql) + (size_t)idx * 32);
#pragma unroll
    for (int j = 0; j < 8; j++) {
        ph[j] = make_uint4(hp[4 * j], hp[4 * j + 1], hp[4 * j + 2], hp[4 * j + 3]);
        pl[j] = make_uint4(lp[4 * j], lp[4 * j + 1], lp[4 * j + 2], lp[4 * j + 3]);
    }
}

// ---------------- phase 1b: v split ----------------
__global__ __launch_bounds__(256) void vsplit_kernel(const float* __restrict__ v) {
    int i = blockIdx.x * blockDim.x + threadIdx.x;
    int total = B_ * C_ * NN / 2;
    if (i >= total) return;
    float2 p = reinterpret_cast<const float2*>(v)[i];
    reinterpret_cast<uint32_t*>(g_vh)[i] = hipack(p.x, p.y);
    reinterpret_cast<uint32_t*>(g_vl)[i] = lopack(p.x, p.y);
}

// ---------------- tile loaders ----------------
// 128 rows x 128B contiguous -> swizzled smem
static __device__ __forceinline__ void load_tile_lin(char* smem, int soff,
                                                     const char* g, int tid) {
#pragma unroll
    for (int k = 0; k < 4; k++) {
        int i = tid + k * 256;
        uint4 val = *reinterpret_cast<const uint4*>(g + (size_t)i * 16);
        *reinterpret_cast<uint4*>(smem + soff + swz((uint32_t)i * 16)) = val;
    }
}
// V tile: 64 rows (c) x 256B (128 m bf16), row stride NN*2 -> two swizzled 128B subtiles
static __device__ __forceinline__ void load_v_tile(char* smem, int soff,
                                                   const char* g, int tid) {
#pragma unroll
    for (int k = 0; k < 4; k++) {
        int i = tid + k * 256;
        int c = i >> 4, j = i & 15;
        uint4 val = *reinterpret_cast<const uint4*>(g + (size_t)c * (NN * 2) + j * 16);
        int sub = j >> 3;
        *reinterpret_cast<uint4*>(smem + soff + sub * 8192 + swz((uint32_t)(c * 128 + (j & 7) * 16))) = val;
    }
}

// ---------------- S = Qn * Qm^T (3-term bf16 split), per-warp 16x128 ----------------
static __device__ __forceinline__ void compute_S(float (&C)[16][4],
                                                 uint32_t sAH, uint32_t sAL,
                                                 uint32_t sBH, uint32_t sBL,
                                                 int lane, int rowA0) {
#pragma unroll
    for (int j = 0; j < 16; j++) {
        C[j][0] = 0.f; C[j][1] = 0.f; C[j][2] = 0.f; C[j][3] = 0.f;
    }
    int rowA = rowA0 + (lane & 15);
    int kc = (lane >> 4) * 16;
    int rowB = lane & 15;
#pragma unroll
    for (int ks = 0; ks < 4; ks++) {
        uint32_t aoff = swz((uint32_t)(rowA * 128 + ks * 32 + kc));
        uint32_t aH[4], aL[4];
        ldsm4(aH[0], aH[1], aH[2], aH[3], sAH + aoff);
        ldsm4(aL[0], aL[1], aL[2], aL[3], sAL + aoff);
#pragma unroll
        for (int p = 0; p < 8; p++) {
            uint32_t boff = swz((uint32_t)((p * 16 + rowB) * 128 + ks * 32 + kc));
            uint32_t b0, b1, b2, b3;
            ldsm4(b0, b1, b2, b3, sBH + boff);
            mma_bf16(C[2 * p],     aH, b0, b2);
            mma_bf16(C[2 * p + 1], aH, b1, b3);
            mma_bf16(C[2 * p],     aL, b0, b2);
            mma_bf16(C[2 * p + 1], aL, b1, b3);
            ldsm4(b0, b1, b2, b3, sBL + boff);
            mma_bf16(C[2 * p],     aH, b0, b2);
            mma_bf16(C[2 * p + 1], aH, b1, b3);
        }
    }
}

// ---------------- pass A: rowsums ----------------
#define A_AH 0
#define A_AL 16384
#define A_BH 32768
#define A_BL 49152
#define A_SMEM 65536

__global__ __launch_bounds__(256, 1) void rowsum_kernel(const float* __restrict__ bg_p) {
    extern __shared__ char smem[];
    uint32_t sb = smem_u32(smem);
    int tid = threadIdx.x, wid = tid >> 5, lane = tid & 31;
    int b = blockIdx.y, n0 = blockIdx.x * NBLK;
    float bg = *bg_p, mshift = -fabsf(bg);

    load_tile_lin(smem, A_AH, (const char*)g_qh + ((size_t)b * NN + n0) * 128, tid);
    load_tile_lin(smem, A_AL, (const char*)g_ql + ((size_t)b * NN + n0) * 128, tid);

    float r0 = 0.f, r1 = 0.f;
    float C[16][4];
    for (int mt = 0; mt < NT_M; mt++) {
        int m0 = mt * MT;
        __syncthreads();
        load_tile_lin(smem, A_BH, (const char*)g_qh + ((size_t)b * NN + m0) * 128, tid);
        load_tile_lin(smem, A_BL, (const char*)g_ql + ((size_t)b * NN + m0) * 128, tid);
        __syncthreads();
        compute_S(C, sb + A_AH, sb + A_AL, sb + A_BH, sb + A_BL, lane, wid * 16);
#pragma unroll
        for (int j = 0; j < 16; j++) {
            r0 += __expf(fmaf(C[j][0], bg, mshift)) + __expf(fmaf(C[j][1], bg, mshift));
            r1 += __expf(fmaf(C[j][2], bg, mshift)) + __expf(fmaf(C[j][3], bg, mshift));
        }
    }
    r0 += __shfl_xor_sync(0xffffffffu, r0, 1);
    r0 += __shfl_xor_sync(0xffffffffu, r0, 2);
    r1 += __shfl_xor_sync(0xffffffffu, r1, 1);
    r1 += __shfl_xor_sync(0xffffffffu, r1, 2);
    if ((lane & 3) == 0) {
        int n = n0 + wid * 16 + (lane >> 2);
        g_inv[b * NN + n]     = 1.0f / r0;
        g_inv[b * NN + n + 8] = 1.0f / r1;
    }
}

// ---------------- pass B: beta + O ----------------
#define P_AH 0
#define P_AL 16384
#define P_BH 32768
#define P_BL 49152
#define P_VH 65536
#define P_VL 81920
#define P_SMEM 98304

__global__ __launch_bounds__(256, 1) void attn_kernel(float* __restrict__ out,
                                                      float* __restrict__ beta,
                                                      const float* __restrict__ v,
                                                      const float* __restrict__ bg_p,
                                                      const float* __restrict__ sg0_p,
                                                      const float* __restrict__ sg1_p) {
    extern __shared__ char smem[];
    uint32_t sb = smem_u32(smem);
    int tid = threadIdx.x, wid = tid >> 5, lane = tid & 31;
    int b = blockIdx.y, n0 = blockIdx.x * NBLK;
    float bg = *bg_p, mshift = -fabsf(bg);

    load_tile_lin(smem, P_AH, (const char*)g_qh + ((size_t)b * NN + n0) * 128, tid);
    load_tile_lin(smem, P_AL, (const char*)g_ql + ((size_t)b * NN + n0) * 128, tid);

    int nrow0 = n0 + wid * 16 + (lane >> 2);     // row for c0/c1
    float inv0 = g_inv[b * NN + nrow0];
    float inv1 = g_inv[b * NN + nrow0 + 8];
    float* betaRow0 = beta + ((size_t)b * NN + nrow0) * NN + (lane & 3) * 2;
    float* betaRow1 = betaRow0 + (size_t)8 * NN;

    float O[8][4];
#pragma unroll
    for (int q = 0; q < 8; q++) { O[q][0] = O[q][1] = O[q][2] = O[q][3] = 0.f; }

    float C[16][4];
    int kc = (lane >> 4) * 16;
    int rowB = lane & 15;

    for (int mt = 0; mt < NT_M; mt++) {
        int m0 = mt * MT;
        __syncthreads();
        load_tile_lin(smem, P_BH, (const char*)g_qh + ((size_t)b * NN + m0) * 128, tid);
        load_tile_lin(smem, P_BL, (const char*)g_ql + ((size_t)b * NN + m0) * 128, tid);
        load_v_tile(smem, P_VH, (const char*)g_vh + ((size_t)b * C_ * NN + m0) * 2, tid);
        load_v_tile(smem, P_VL, (const char*)g_vl + ((size_t)b * C_ * NN + m0) * 2, tid);
        __syncthreads();

        compute_S(C, sb + P_AH, sb + P_AL, sb + P_BH, sb + P_BL, lane, wid * 16);

        // exp + normalize + write beta
#pragma unroll
        for (int j = 0; j < 16; j++) {
            float e0 = __expf(fmaf(C[j][0], bg, mshift)) * inv0;
            float e1 = __expf(fmaf(C[j][1], bg, mshift)) * inv0;
            float e2 = __expf(fmaf(C[j][2], bg, mshift)) * inv1;
            float e3 = __expf(fmaf(C[j][3], bg, mshift)) * inv1;
            C[j][0] = e0; C[j][1] = e1; C[j][2] = e2; C[j][3] = e3;
            *reinterpret_cast<float2*>(betaRow0 + m0 + j * 8) = make_float2(e0, e1);
            *reinterpret_cast<float2*>(betaRow1 + m0 + j * 8) = make_float2(e2, e3);
        }

        // O += P * V^T  (P from C frags, V from smem)
#pragma unroll
        for (int kk = 0; kk < 8; kk++) {
            uint32_t pH[4], pL[4];
            pH[0] = hipack(C[2 * kk][0],     C[2 * kk][1]);
            pH[1] = hipack(C[2 * kk][2],     C[2 * kk][3]);
            pH[2] = hipack(C[2 * kk + 1][0], C[2 * kk + 1][1]);
            pH[3] = hipack(C[2 * kk + 1][2], C[2 * kk + 1][3]);
            pL[0] = lopack(C[2 * kk][0],     C[2 * kk][1]);
            pL[1] = lopack(C[2 * kk][2],     C[2 * kk][3]);
            pL[2] = lopack(C[2 * kk + 1][0], C[2 * kk + 1][1]);
            pL[3] = lopack(C[2 * kk + 1][2], C[2 * kk + 1][3]);
            uint32_t vbase = (kk >> 2) * 8192 + (uint32_t)((kk & 3) * 32 + kc);
#pragma unroll
            for (int q = 0; q < 4; q++) {
                uint32_t boff = swz((uint32_t)((q * 16 + rowB) * 128) + vbase);
                uint32_t b0, b1, b2, b3;
                ldsm4(b0, b1, b2, b3, sb + P_VH + boff);
                mma_bf16(O[2 * q],     pH, b0, b2);
                mma_bf16(O[2 * q + 1], pH, b1, b3);
                mma_bf16(O[2 * q],     pL, b0, b2);
                mma_bf16(O[2 * q + 1], pL, b1, b3);
                ldsm4(b0, b1, b2, b3, sb + P_VL + boff);
                mma_bf16(O[2 * q],     pH, b0, b2);
                mma_bf16(O[2 * q + 1], pH, b1, b3);
            }
        }
    }

    // epilogue: out = w0*o + w1*v   (o already normalized since P was)
    float eg0 = __expf(*sg0_p), eg1 = __expf(*sg1_p);
    float tot = eg0 + eg1;
    float w0 = eg0 / tot, w1 = eg1 / tot;
    int nr0 = n0 + wid * 16 + (lane >> 2);
#pragma unroll
    for (int q = 0; q < 8; q++) {
        int c = q * 8 + (lane & 3) * 2;
        size_t base0 = ((size_t)b * C_ + c) * NN + nr0;
        out[base0]          = w0 * O[q][0] + w1 * v[base0];
        out[base0 + NN]     = w0 * O[q][1] + w1 * v[base0 + NN];
        out[base0 + 8]      = w0 * O[q][2] + w1 * v[base0 + 8];
        out[base0 + NN + 8] = w0 * O[q][3] + w1 * v[base0 + NN + 8];
    }
}

// ---------------- launch ----------------
extern "C" void kernel_launch(void* const* d_in, const int* in_sizes, int n_in,
                              void* d_out, int out_size) {
    const float* x     = (const float*)d_in[0];
    const float* v     = (const float*)d_in[1];
    const float* pos   = (const float*)d_in[2];
    const float* gamma = (const float*)d_in[3];
    const float* bg    = (const float*)d_in[4];
    const float* sg0   = (const float*)d_in[5];
    const float* sg1   = (const float*)d_in[6];

    float* out  = (float*)d_out;
    float* beta = out + (size_t)B_ * C_ * NN;

    cudaFuncSetAttribute(rowsum_kernel, cudaFuncAttributeMaxDynamicSharedMemorySize, A_SMEM);
    cudaFuncSetAttribute(attn_kernel,   cudaFuncAttributeMaxDynamicSharedMemorySize, P_SMEM);

    qsplit_kernel<<<(B_ * NN + 255) / 256, 256>>>(x, pos, gamma);
    vsplit_kernel<<<(B_ * C_ * NN / 2 + 255) / 256, 256>>>(v);

    dim3 grid(NT_N, B_);
    rowsum_kernel<<<grid, 256, A_SMEM>>>(bg);
    attn_kernel<<<grid, 256, P_SMEM>>>(out, beta, v, bg, sg0, sg1);
}

// round 4
// speedup vs baseline: 2.3342x; 1.1307x over previous
#include <cuda_runtime.h>
#include <math.h>
#include <stdint.h>

#define B_   8
#define C_   64
#define NN   2304          // 48*48
#define NBLK 128           // n rows per CTA
#define MT   128           // m per tile
#define NT_M 18
#define NT_N 18

// ---------------- scratch ----------------
__device__ unsigned short g_qh[B_ * NN * C_];   // [b][n][c] bf16 hi
__device__ unsigned short g_ql[B_ * NN * C_];   // residual
__device__ unsigned short g_vh[B_ * C_ * NN];   // [b][c][m]
__device__ unsigned short g_vl[B_ * C_ * NN];
__device__ float          g_inv[B_ * NN];       // 1 / rowsum

// ---------------- helpers ----------------
static __device__ __forceinline__ uint32_t smem_u32(const void* p) {
    uint32_t a;
    asm("{ .reg .u64 t; cvta.to.shared.u64 t, %1; cvt.u32.u64 %0, t; }" : "=r"(a) : "l"(p));
    return a;
}
static __device__ __forceinline__ uint32_t swz(uint32_t o) { return o ^ ((o >> 3) & 0x70u); }

static __device__ __forceinline__ void ldsm4(uint32_t& r0, uint32_t& r1,
                                             uint32_t& r2, uint32_t& r3, uint32_t a) {
    asm volatile("ldmatrix.sync.aligned.m8n8.x4.shared.b16 {%0,%1,%2,%3}, [%4];"
                 : "=r"(r0), "=r"(r1), "=r"(r2), "=r"(r3) : "r"(a));
}
static __device__ __forceinline__ void mma_bf16(float (&d)[4], const uint32_t (&a)[4],
                                                uint32_t b0, uint32_t b1) {
    asm volatile(
        "mma.sync.aligned.m16n8k16.row.col.f32.bf16.bf16.f32 "
        "{%0,%1,%2,%3}, {%4,%5,%6,%7}, {%8,%9}, {%0,%1,%2,%3};"
        : "+f"(d[0]), "+f"(d[1]), "+f"(d[2]), "+f"(d[3])
        : "r"(a[0]), "r"(a[1]), "r"(a[2]), "r"(a[3]), "r"(b0), "r"(b1));
}
static __device__ __forceinline__ uint32_t hipack(float x, float y) {
    return __byte_perm(__float_as_uint(x), __float_as_uint(y), 0x7632);
}
static __device__ __forceinline__ uint32_t lopack(float x, float y) {
    float rx = x - __uint_as_float(__float_as_uint(x) & 0xFFFF0000u);
    float ry = y - __uint_as_float(__float_as_uint(y) & 0xFFFF0000u);
    uint32_t r;
    asm("cvt.rn.bf16x2.f32 %0, %1, %2;" : "=r"(r) : "f"(ry), "f"(rx));
    return r;
}

// ---------------- cp.async ----------------
#define CP16(dst, src) \
    asm volatile("cp.async.cg.shared.global [%0], [%1], 16;" :: "r"(dst), "l"(src))
#define CP_COMMIT()  asm volatile("cp.async.commit_group;" ::: "memory")
#define CP_WAIT(n)   asm volatile("cp.async.wait_group %0;" :: "n"(n) : "memory")

// 128 rows x 128B contiguous -> swizzled smem (async)
static __device__ __forceinline__ void cp_tile_lin(uint32_t sdst, const char* g, int tid) {
#pragma unroll
    for (int k = 0; k < 4; k++) {
        int i = tid + k * 256;
        CP16(sdst + swz((uint32_t)i * 16), g + (size_t)i * 16);
    }
}
// V tile: 64 rows (c) x 256B (128 m bf16), stride NN*2 -> two swizzled 128B subtiles
static __device__ __forceinline__ void cp_v_tile(uint32_t sdst, const char* g, int tid) {
#pragma unroll
    for (int k = 0; k < 4; k++) {
        int i = tid + k * 256;
        int c = i >> 4, j = i & 15;
        int sub = j >> 3;
        CP16(sdst + sub * 8192 + swz((uint32_t)(c * 128 + (j & 7) * 16)),
             g + (size_t)c * (NN * 2) + j * 16);
    }
}

// ---------------- phase 1a: q split ----------------
__global__ __launch_bounds__(256) void qsplit_kernel(const float* __restrict__ x,
                                                     const float* __restrict__ pos,
                                                     const float* __restrict__ gamma_p) {
    int idx = blockIdx.x * blockDim.x + threadIdx.x;
    if (idx >= B_ * NN) return;
    int b = idx / NN, n = idx - b * NN;
    float gamma = *gamma_p;
    const float* xb = x   + (size_t)b * C_ * NN + n;
    const float* pb = pos + (size_t)b * C_ * NN + n;
    float q[C_]; float s = 0.f;
#pragma unroll
    for (int c = 0; c < C_; c++) {
        float v = xb[(size_t)c * NN] + gamma * pb[(size_t)c * NN];
        q[c] = v; s += v * v;
    }
    float inv = 1.0f / sqrtf(s + 1e-6f);
    uint32_t hp[32], lp[32];
#pragma unroll
    for (int i = 0; i < 32; i++) {
        float a = q[2 * i] * inv, bv = q[2 * i + 1] * inv;
        hp[i] = hipack(a, bv);
        lp[i] = lopack(a, bv);
    }
    uint4* ph = reinterpret_cast<uint4*>(reinterpret_cast<uint32_t*>(g_qh) + (size_t)idx * 32);
    uint4* pl = reinterpret_cast<uint4*>(reinterpret_cast<uint32_t*>(g_ql) + (size_t)idx * 32);
#pragma unroll
    for (int j = 0; j < 8; j++) {
        ph[j] = make_uint4(hp[4 * j], hp[4 * j + 1], hp[4 * j + 2], hp[4 * j + 3]);
        pl[j] = make_uint4(lp[4 * j], lp[4 * j + 1], lp[4 * j + 2], lp[4 * j + 3]);
    }
}

// ---------------- phase 1b: v split ----------------
__global__ __launch_bounds__(256) void vsplit_kernel(const float* __restrict__ v) {
    int i = blockIdx.x * blockDim.x + threadIdx.x;
    int total = B_ * C_ * NN / 2;
    if (i >= total) return;
    float2 p = reinterpret_cast<const float2*>(v)[i];
    reinterpret_cast<uint32_t*>(g_vh)[i] = hipack(p.x, p.y);
    reinterpret_cast<uint32_t*>(g_vl)[i] = lopack(p.x, p.y);
}

// ---------------- S = Qn * Qm^T (3-term bf16 split), per-warp 16x128 ----------------
static __device__ __forceinline__ void compute_S(float (&C)[16][4],
                                                 uint32_t sAH, uint32_t sAL,
                                                 uint32_t sBH, uint32_t sBL,
                                                 int lane, int rowA0) {
#pragma unroll
    for (int j = 0; j < 16; j++) {
        C[j][0] = 0.f; C[j][1] = 0.f; C[j][2] = 0.f; C[j][3] = 0.f;
    }
    int rowA = rowA0 + (lane & 15);
    int kc = (lane >> 4) * 16;
    int rowB = lane & 15;
#pragma unroll
    for (int ks = 0; ks < 4; ks++) {
        uint32_t aoff = swz((uint32_t)(rowA * 128 + ks * 32 + kc));
        uint32_t aH[4], aL[4];
        ldsm4(aH[0], aH[1], aH[2], aH[3], sAH + aoff);
        ldsm4(aL[0], aL[1], aL[2], aL[3], sAL + aoff);
#pragma unroll
        for (int p = 0; p < 8; p++) {
            uint32_t boff = swz((uint32_t)((p * 16 + rowB) * 128 + ks * 32 + kc));
            uint32_t b0, b1, b2, b3;
            ldsm4(b0, b1, b2, b3, sBH + boff);
            mma_bf16(C[2 * p],     aH, b0, b2);
            mma_bf16(C[2 * p + 1], aH, b1, b3);
            mma_bf16(C[2 * p],     aL, b0, b2);
            mma_bf16(C[2 * p + 1], aL, b1, b3);
            ldsm4(b0, b1, b2, b3, sBL + boff);
            mma_bf16(C[2 * p],     aH, b0, b2);
            mma_bf16(C[2 * p + 1], aH, b1, b3);
        }
    }
}

// ---------------- pass A: rowsums (2-stage cp.async pipeline) ----------------
#define A_AH 0
#define A_AL 16384
#define A_BH 32768          // [2] double buffer, +16384*s
#define A_BL 65536          // [2]
#define A_SMEM 98304

__global__ __launch_bounds__(256, 1) void rowsum_kernel(const float* __restrict__ bg_p) {
    extern __shared__ char smem[];
    uint32_t sb = smem_u32(smem);
    int tid = threadIdx.x, wid = tid >> 5, lane = tid & 31;
    int b = blockIdx.y, n0 = blockIdx.x * NBLK;
    float bg = *bg_p, mshift = -fabsf(bg);

    const char* qhB = (const char*)g_qh + (size_t)b * NN * 128;
    const char* qlB = (const char*)g_ql + (size_t)b * NN * 128;

    // A tiles + first B tile, async
    cp_tile_lin(sb + A_AH, qhB + (size_t)n0 * 128, tid);
    cp_tile_lin(sb + A_AL, qlB + (size_t)n0 * 128, tid);
    CP_COMMIT();
    cp_tile_lin(sb + A_BH, qhB, tid);
    cp_tile_lin(sb + A_BL, qlB, tid);
    CP_COMMIT();

    float r0 = 0.f, r1 = 0.f;
    float C[16][4];
    for (int mt = 0; mt < NT_M; mt++) {
        int cur = mt & 1;
        if (mt + 1 < NT_M) {
            int nxt = cur ^ 1;
            cp_tile_lin(sb + A_BH + nxt * 16384, qhB + (size_t)(mt + 1) * MT * 128, tid);
            cp_tile_lin(sb + A_BL + nxt * 16384, qlB + (size_t)(mt + 1) * MT * 128, tid);
            CP_COMMIT();
            CP_WAIT(1);
        } else {
            CP_WAIT(0);
        }
        __syncthreads();
        compute_S(C, sb + A_AH, sb + A_AL,
                  sb + A_BH + cur * 16384, sb + A_BL + cur * 16384, lane, wid * 16);
        __syncthreads();
#pragma unroll
        for (int j = 0; j < 16; j++) {
            r0 += __expf(fmaf(C[j][0], bg, mshift)) + __expf(fmaf(C[j][1], bg, mshift));
            r1 += __expf(fmaf(C[j][2], bg, mshift)) + __expf(fmaf(C[j][3], bg, mshift));
        }
    }
    r0 += __shfl_xor_sync(0xffffffffu, r0, 1);
    r0 += __shfl_xor_sync(0xffffffffu, r0, 2);
    r1 += __shfl_xor_sync(0xffffffffu, r1, 1);
    r1 += __shfl_xor_sync(0xffffffffu, r1, 2);
    if ((lane & 3) == 0) {
        int n = n0 + wid * 16 + (lane >> 2);
        g_inv[b * NN + n]     = 1.0f / r0;
        g_inv[b * NN + n + 8] = 1.0f / r1;
    }
}

// ---------------- pass B: beta + O (2-stage cp.async pipeline) ----------------
#define P_AH 0
#define P_AL 16384
#define P_BH 32768          // [2]
#define P_BL 65536          // [2]
#define P_VH 98304          // [2]
#define P_VL 131072         // [2]
#define P_SMEM 163840

__global__ __launch_bounds__(256, 1) void attn_kernel(float* __restrict__ out,
                                                      float* __restrict__ beta,
                                                      const float* __restrict__ v,
                                                      const float* __restrict__ bg_p,
                                                      const float* __restrict__ sg0_p,
                                                      const float* __restrict__ sg1_p) {
    extern __shared__ char smem[];
    uint32_t sb = smem_u32(smem);
    int tid = threadIdx.x, wid = tid >> 5, lane = tid & 31;
    int b = blockIdx.y, n0 = blockIdx.x * NBLK;
    float bg = *bg_p, mshift = -fabsf(bg);

    const char* qhB = (const char*)g_qh + (size_t)b * NN * 128;
    const char* qlB = (const char*)g_ql + (size_t)b * NN * 128;
    const char* vhB = (const char*)g_vh + (size_t)b * C_ * NN * 2;
    const char* vlB = (const char*)g_vl + (size_t)b * C_ * NN * 2;

    cp_tile_lin(sb + P_AH, qhB + (size_t)n0 * 128, tid);
    cp_tile_lin(sb + P_AL, qlB + (size_t)n0 * 128, tid);
    CP_COMMIT();
    cp_tile_lin(sb + P_BH, qhB, tid);
    cp_tile_lin(sb + P_BL, qlB, tid);
    cp_v_tile(sb + P_VH, vhB, tid);
    cp_v_tile(sb + P_VL, vlB, tid);
    CP_COMMIT();

    int nrow0 = n0 + wid * 16 + (lane >> 2);
    float inv0 = g_inv[b * NN + nrow0];
    float inv1 = g_inv[b * NN + nrow0 + 8];
    float* betaRow0 = beta + ((size_t)b * NN + nrow0) * NN + (lane & 3) * 2;
    float* betaRow1 = betaRow0 + (size_t)8 * NN;

    float O[8][4];
#pragma unroll
    for (int q = 0; q < 8; q++) { O[q][0] = O[q][1] = O[q][2] = O[q][3] = 0.f; }

    float C[16][4];
    int kc = (lane >> 4) * 16;
    int rowB = lane & 15;

    for (int mt = 0; mt < NT_M; mt++) {
        int m0 = mt * MT;
        int cur = mt & 1;
        if (mt + 1 < NT_M) {
            int nxt = cur ^ 1;
            cp_tile_lin(sb + P_BH + nxt * 16384, qhB + (size_t)(m0 + MT) * 128, tid);
            cp_tile_lin(sb + P_BL + nxt * 16384, qlB + (size_t)(m0 + MT) * 128, tid);
            cp_v_tile(sb + P_VH + nxt * 16384, vhB + (size_t)(m0 + MT) * 2, tid);
            cp_v_tile(sb + P_VL + nxt * 16384, vlB + (size_t)(m0 + MT) * 2, tid);
            CP_COMMIT();
            CP_WAIT(1);
        } else {
            CP_WAIT(0);
        }
        __syncthreads();

        compute_S(C, sb + P_AH, sb + P_AL,
                  sb + P_BH + cur * 16384, sb + P_BL + cur * 16384, lane, wid * 16);

        // exp + normalize + write beta
#pragma unroll
        for (int j = 0; j < 16; j++) {
            float e0 = __expf(fmaf(C[j][0], bg, mshift)) * inv0;
            float e1 = __expf(fmaf(C[j][1], bg, mshift)) * inv0;
            float e2 = __expf(fmaf(C[j][2], bg, mshift)) * inv1;
            float e3 = __expf(fmaf(C[j][3], bg, mshift)) * inv1;
            C[j][0] = e0; C[j][1] = e1; C[j][2] = e2; C[j][3] = e3;
            *reinterpret_cast<float2*>(betaRow0 + m0 + j * 8) = make_float2(e0, e1);
            *reinterpret_cast<float2*>(betaRow1 + m0 + j * 8) = make_float2(e2, e3);
        }

        // O += P * V^T
        uint32_t vH = sb + P_VH + cur * 16384;
        uint32_t vL = sb + P_VL + cur * 16384;
#pragma unroll
        for (int kk = 0; kk < 8; kk++) {
            uint32_t pH[4], pL[4];
            pH[0] = hipack(C[2 * kk][0],     C[2 * kk][1]);
            pH[1] = hipack(C[2 * kk][2],     C[2 * kk][3]);
            pH[2] = hipack(C[2 * kk + 1][0], C[2 * kk + 1][1]);
            pH[3] = hipack(C[2 * kk + 1][2], C[2 * kk + 1][3]);
            pL[0] = lopack(C[2 * kk][0],     C[2 * kk][1]);
            pL[1] = lopack(C[2 * kk][2],     C[2 * kk][3]);
            pL[2] = lopack(C[2 * kk + 1][0], C[2 * kk + 1][1]);
            pL[3] = lopack(C[2 * kk + 1][2], C[2 * kk + 1][3]);
            uint32_t vbase = (kk >> 2) * 8192 + (uint32_t)((kk & 3) * 32 + kc);
#pragma unroll
            for (int q = 0; q < 4; q++) {
                uint32_t boff = swz((uint32_t)((q * 16 + rowB) * 128) + vbase);
                uint32_t b0, b1, b2, b3;
                ldsm4(b0, b1, b2, b3, vH + boff);
                mma_bf16(O[2 * q],     pH, b0, b2);
                mma_bf16(O[2 * q + 1], pH, b1, b3);
                mma_bf16(O[2 * q],     pL, b0, b2);
                mma_bf16(O[2 * q + 1], pL, b1, b3);
                ldsm4(b0, b1, b2, b3, vL + boff);
                mma_bf16(O[2 * q],     pH, b0, b2);
                mma_bf16(O[2 * q + 1], pH, b1, b3);
            }
        }
        __syncthreads();
    }

    // epilogue: out = w0*o + w1*v
    float eg0 = __expf(*sg0_p), eg1 = __expf(*sg1_p);
    float tot = eg0 + eg1;
    float w0 = eg0 / tot, w1 = eg1 / tot;
    int nr0 = n0 + wid * 16 + (lane >> 2);
#pragma unroll
    for (int q = 0; q < 8; q++) {
        int c = q * 8 + (lane & 3) * 2;
        size_t base0 = ((size_t)b * C_ + c) * NN + nr0;
        out[base0]          = w0 * O[q][0] + w1 * v[base0];
        out[base0 + NN]     = w0 * O[q][1] + w1 * v[base0 + NN];
        out[base0 + 8]      = w0 * O[q][2] + w1 * v[base0 + 8];
        out[base0 + NN + 8] = w0 * O[q][3] + w1 * v[base0 + NN + 8];
    }
}

// ---------------- launch ----------------
extern "C" void kernel_launch(void* const* d_in, const int* in_sizes, int n_in,
                              void* d_out, int out_size) {
    const float* x     = (const float*)d_in[0];
    const float* v     = (const float*)d_in[1];
    const float* pos   = (const float*)d_in[2];
    const float* gamma = (const float*)d_in[3];
    const float* bg    = (const float*)d_in[4];
    const float* sg0   = (const float*)d_in[5];
    const float* sg1   = (const float*)d_in[6];

    float* out  = (float*)d_out;
    float* beta = out + (size_t)B_ * C_ * NN;

    cudaFuncSetAttribute(rowsum_kernel, cudaFuncAttributeMaxDynamicSharedMemorySize, A_SMEM);
    cudaFuncSetAttribute(attn_kernel,   cudaFuncAttributeMaxDynamicSharedMemorySize, P_SMEM);

    qsplit_kernel<<<(B_ * NN + 255) / 256, 256>>>(x, pos, gamma);
    vsplit_kernel<<<(B_ * C_ * NN / 2 + 255) / 256, 256>>>(v);

    dim3 grid(NT_N, B_);
    rowsum_kernel<<<grid, 256, A_SMEM>>>(bg);
    attn_kernel<<<grid, 256, P_SMEM>>>(out, beta, v, bg, sg0, sg1);
}

// round 5
// speedup vs baseline: 2.3867x; 1.0225x over previous
#include <cuda_runtime.h>
#include <math.h>
#include <stdint.h>

#define B_   8
#define C_   64
#define NN   2304          // 48*48
#define NH   1152          // NN/2, m-half
#define NBLK 128           // n rows per CTA
#define NT_N 18

// ---------------- scratch ----------------
__device__ unsigned short g_qh[B_ * NN * C_];   // [b][n][c] bf16 hi
__device__ unsigned short g_ql[B_ * NN * C_];   // residual
__device__ unsigned short g_vh[B_ * C_ * NN];   // [b][c][m]
__device__ unsigned short g_vl[B_ * C_ * NN];
__device__ float          g_sum[B_ * NN];       // rowsum (atomic)
__device__ float          g_o[B_ * C_ * NN];    // O accumulation (atomic)

// ---------------- helpers ----------------
static __device__ __forceinline__ uint32_t smem_u32(const void* p) {
    uint32_t a;
    asm("{ .reg .u64 t; cvta.to.shared.u64 t, %1; cvt.u32.u64 %0, t; }" : "=r"(a) : "l"(p));
    return a;
}
static __device__ __forceinline__ uint32_t swz(uint32_t o) { return o ^ ((o >> 3) & 0x70u); }

static __device__ __forceinline__ void ldsm4(uint32_t& r0, uint32_t& r1,
                                             uint32_t& r2, uint32_t& r3, uint32_t a) {
    asm volatile("ldmatrix.sync.aligned.m8n8.x4.shared.b16 {%0,%1,%2,%3}, [%4];"
                 : "=r"(r0), "=r"(r1), "=r"(r2), "=r"(r3) : "r"(a));
}
static __device__ __forceinline__ void mma_bf16(float (&d)[4], const uint32_t (&a)[4],
                                                uint32_t b0, uint32_t b1) {
    asm volatile(
        "mma.sync.aligned.m16n8k16.row.col.f32.bf16.bf16.f32 "
        "{%0,%1,%2,%3}, {%4,%5,%6,%7}, {%8,%9}, {%0,%1,%2,%3};"
        : "+f"(d[0]), "+f"(d[1]), "+f"(d[2]), "+f"(d[3])
        : "r"(a[0]), "r"(a[1]), "r"(a[2]), "r"(a[3]), "r"(b0), "r"(b1));
}
static __device__ __forceinline__ uint32_t hipack(float x, float y) {
    return __byte_perm(__float_as_uint(x), __float_as_uint(y), 0x7632);
}
static __device__ __forceinline__ uint32_t lopack(float x, float y) {
    float rx = x - __uint_as_float(__float_as_uint(x) & 0xFFFF0000u);
    float ry = y - __uint_as_float(__float_as_uint(y) & 0xFFFF0000u);
    uint32_t r;
    asm("cvt.rn.bf16x2.f32 %0, %1, %2;" : "=r"(r) : "f"(ry), "f"(rx));
    return r;
}

// ---------------- cp.async ----------------
#define CP16(dst, src) \
    asm volatile("cp.async.cg.shared.global [%0], [%1], 16;" :: "r"(dst), "l"(src))
#define CP_COMMIT()  asm volatile("cp.async.commit_group;" ::: "memory")
#define CP_WAIT(n)   asm volatile("cp.async.wait_group %0;" :: "n"(n) : "memory")

// 128 rows x 128B contiguous -> swizzled smem
static __device__ __forceinline__ void cp_tile128(uint32_t sdst, const char* g, int tid) {
#pragma unroll
    for (int k = 0; k < 4; k++) {
        int i = tid + k * 256;
        CP16(sdst + swz((uint32_t)i * 16), g + (size_t)i * 16);
    }
}
// 64 rows x 128B contiguous -> swizzled smem
static __device__ __forceinline__ void cp_tile64(uint32_t sdst, const char* g, int tid) {
#pragma unroll
    for (int k = 0; k < 2; k++) {
        int i = tid + k * 256;
        CP16(sdst + swz((uint32_t)i * 16), g + (size_t)i * 16);
    }
}
// V tile: 64 rows (c) x 128B (64 m bf16), row stride NN*2
static __device__ __forceinline__ void cp_v64(uint32_t sdst, const char* g, int tid) {
#pragma unroll
    for (int k = 0; k < 2; k++) {
        int i = tid + k * 256;
        int c = i >> 3, j = i & 7;
        CP16(sdst + swz((uint32_t)(c * 128 + j * 16)), g + (size_t)c * (NN * 2) + j * 16);
    }
}

// ---------------- phase 1a: q split (+ zero g_sum) ----------------
__global__ __launch_bounds__(256) void qsplit_kernel(const float* __restrict__ x,
                                                     const float* __restrict__ pos,
                                                     const float* __restrict__ gamma_p) {
    int idx = blockIdx.x * blockDim.x + threadIdx.x;
    if (idx >= B_ * NN) return;
    g_sum[idx] = 0.f;
    int b = idx / NN, n = idx - b * NN;
    float gamma = *gamma_p;
    const float* xb = x   + (size_t)b * C_ * NN + n;
    const float* pb = pos + (size_t)b * C_ * NN + n;
    float q[C_]; float s = 0.f;
#pragma unroll
    for (int c = 0; c < C_; c++) {
        float v = xb[(size_t)c * NN] + gamma * pb[(size_t)c * NN];
        q[c] = v; s += v * v;
    }
    float inv = 1.0f / sqrtf(s + 1e-6f);
    uint32_t hp[32], lp[32];
#pragma unroll
    for (int i = 0; i < 32; i++) {
        float a = q[2 * i] * inv, bv = q[2 * i + 1] * inv;
        hp[i] = hipack(a, bv);
        lp[i] = lopack(a, bv);
    }
    uint4* ph = reinterpret_cast<uint4*>(reinterpret_cast<uint32_t*>(g_qh) + (size_t)idx * 32);
    uint4* pl = reinterpret_cast<uint4*>(reinterpret_cast<uint32_t*>(g_ql) + (size_t)idx * 32);
#pragma unroll
    for (int j = 0; j < 8; j++) {
        ph[j] = make_uint4(hp[4 * j], hp[4 * j + 1], hp[4 * j + 2], hp[4 * j + 3]);
        pl[j] = make_uint4(lp[4 * j], lp[4 * j + 1], lp[4 * j + 2], lp[4 * j + 3]);
    }
}

// ---------------- phase 1b: v split (+ zero g_o) ----------------
__global__ __launch_bounds__(256) void vsplit_kernel(const float* __restrict__ v) {
    int i = blockIdx.x * blockDim.x + threadIdx.x;
    int total = B_ * C_ * NN / 2;
    if (i >= total) return;
    float2 p = reinterpret_cast<const float2*>(v)[i];
    reinterpret_cast<uint32_t*>(g_vh)[i] = hipack(p.x, p.y);
    reinterpret_cast<uint32_t*>(g_vl)[i] = lopack(p.x, p.y);
    reinterpret_cast<float2*>(g_o)[i] = make_float2(0.f, 0.f);
}

// ---------------- S tile, MT=128 (rowsum): per-warp 16x128 ----------------
static __device__ __forceinline__ void compute_S128(float (&C)[16][4],
                                                    uint32_t sAH, uint32_t sAL,
                                                    uint32_t sBH, uint32_t sBL,
                                                    int lane, int rowA0) {
#pragma unroll
    for (int j = 0; j < 16; j++) { C[j][0] = C[j][1] = C[j][2] = C[j][3] = 0.f; }
    int rowA = rowA0 + (lane & 15);
    int kc = (lane >> 4) * 16;
    int rowB = lane & 15;
#pragma unroll
    for (int ks = 0; ks < 4; ks++) {
        uint32_t aoff = swz((uint32_t)(rowA * 128 + ks * 32 + kc));
        uint32_t aH[4], aL[4];
        ldsm4(aH[0], aH[1], aH[2], aH[3], sAH + aoff);
        ldsm4(aL[0], aL[1], aL[2], aL[3], sAL + aoff);
#pragma unroll
        for (int p = 0; p < 8; p++) {
            uint32_t boff = swz((uint32_t)((p * 16 + rowB) * 128 + ks * 32 + kc));
            uint32_t b0, b1, b2, b3;
            ldsm4(b0, b1, b2, b3, sBH + boff);
            mma_bf16(C[2 * p],     aH, b0, b2);
            mma_bf16(C[2 * p + 1], aH, b1, b3);
            mma_bf16(C[2 * p],     aL, b0, b2);
            mma_bf16(C[2 * p + 1], aL, b1, b3);
            ldsm4(b0, b1, b2, b3, sBL + boff);
            mma_bf16(C[2 * p],     aH, b0, b2);
            mma_bf16(C[2 * p + 1], aH, b1, b3);
        }
    }
}

// ---------------- S tile, MT=64 (attn): per-warp 16x64 ----------------
static __device__ __forceinline__ void compute_S64(float (&C)[8][4],
                                                   uint32_t sAH, uint32_t sAL,
                                                   uint32_t sBH, uint32_t sBL,
                                                   int lane, int rowA0) {
#pragma unroll
    for (int j = 0; j < 8; j++) { C[j][0] = C[j][1] = C[j][2] = C[j][3] = 0.f; }
    int rowA = rowA0 + (lane & 15);
    int kc = (lane >> 4) * 16;
    int rowB = lane & 15;
#pragma unroll
    for (int ks = 0; ks < 4; ks++) {
        uint32_t aoff = swz((uint32_t)(rowA * 128 + ks * 32 + kc));
        uint32_t aH[4], aL[4];
        ldsm4(aH[0], aH[1], aH[2], aH[3], sAH + aoff);
        ldsm4(aL[0], aL[1], aL[2], aL[3], sAL + aoff);
#pragma unroll
        for (int p = 0; p < 4; p++) {
            uint32_t boff = swz((uint32_t)((p * 16 + rowB) * 128 + ks * 32 + kc));
            uint32_t b0, b1, b2, b3;
            ldsm4(b0, b1, b2, b3, sBH + boff);
            mma_bf16(C[2 * p],     aH, b0, b2);
            mma_bf16(C[2 * p + 1], aH, b1, b3);
            mma_bf16(C[2 * p],     aL, b0, b2);
            mma_bf16(C[2 * p + 1], aL, b1, b3);
            ldsm4(b0, b1, b2, b3, sBL + boff);
            mma_bf16(C[2 * p],     aH, b0, b2);
            mma_bf16(C[2 * p + 1], aH, b1, b3);
        }
    }
}

// ---------------- pass A: rowsums, grid (18, 2, 8), MT=128, 9 tiles ----------------
#define A_AH 0
#define A_AL 16384
#define A_BH 32768          // [2] +16384*s
#define A_BL 65536          // [2]
#define A_SMEM 98304

__global__ __launch_bounds__(256, 2) void rowsum_kernel(const float* __restrict__ bg_p) {
    extern __shared__ char smem[];
    uint32_t sb = smem_u32(smem);
    int tid = threadIdx.x, wid = tid >> 5, lane = tid & 31;
    int b = blockIdx.z, n0 = blockIdx.x * NBLK, mbase = blockIdx.y * NH;
    float bg = *bg_p, mshift = -fabsf(bg);

    const char* qhB = (const char*)g_qh + (size_t)b * NN * 128;
    const char* qlB = (const char*)g_ql + (size_t)b * NN * 128;

    cp_tile128(sb + A_AH, qhB + (size_t)n0 * 128, tid);
    cp_tile128(sb + A_AL, qlB + (size_t)n0 * 128, tid);
    CP_COMMIT();
    cp_tile128(sb + A_BH, qhB + (size_t)mbase * 128, tid);
    cp_tile128(sb + A_BL, qlB + (size_t)mbase * 128, tid);
    CP_COMMIT();

    float r0 = 0.f, r1 = 0.f;
    float C[16][4];
    for (int mt = 0; mt < 9; mt++) {
        int cur = mt & 1;
        if (mt + 1 < 9) {
            int nxt = cur ^ 1;
            cp_tile128(sb + A_BH + nxt * 16384, qhB + (size_t)(mbase + (mt + 1) * 128) * 128, tid);
            cp_tile128(sb + A_BL + nxt * 16384, qlB + (size_t)(mbase + (mt + 1) * 128) * 128, tid);
            CP_COMMIT();
            CP_WAIT(1);
        } else {
            CP_WAIT(0);
        }
        __syncthreads();
        compute_S128(C, sb + A_AH, sb + A_AL,
                     sb + A_BH + cur * 16384, sb + A_BL + cur * 16384, lane, wid * 16);
        __syncthreads();
#pragma unroll
        for (int j = 0; j < 16; j++) {
            r0 += __expf(fmaf(C[j][0], bg, mshift)) + __expf(fmaf(C[j][1], bg, mshift));
            r1 += __expf(fmaf(C[j][2], bg, mshift)) + __expf(fmaf(C[j][3], bg, mshift));
        }
    }
    r0 += __shfl_xor_sync(0xffffffffu, r0, 1);
    r0 += __shfl_xor_sync(0xffffffffu, r0, 2);
    r1 += __shfl_xor_sync(0xffffffffu, r1, 1);
    r1 += __shfl_xor_sync(0xffffffffu, r1, 2);
    if ((lane & 3) == 0) {
        int n = n0 + wid * 16 + (lane >> 2);
        atomicAdd(&g_sum[b * NN + n], r0);
        atomicAdd(&g_sum[b * NN + n + 8], r1);
    }
}

// ---------------- pass B: beta + O, grid (18, 2, 8), MT=64, 18 tiles ----------------
#define P_AH 0
#define P_AL 16384
#define P_BH 32768          // [2] +8192*s
#define P_BL 49152          // [2]
#define P_VH 65536          // [2]
#define P_VL 81920          // [2]
#define P_SMEM 98304

__global__ __launch_bounds__(256, 2) void attn_kernel(float* __restrict__ beta,
                                                      const float* __restrict__ bg_p) {
    extern __shared__ char smem[];
    uint32_t sb = smem_u32(smem);
    int tid = threadIdx.x, wid = tid >> 5, lane = tid & 31;
    int b = blockIdx.z, n0 = blockIdx.x * NBLK, mbase = blockIdx.y * NH;
    float bg = *bg_p, mshift = -fabsf(bg);

    const char* qhB = (const char*)g_qh + (size_t)b * NN * 128;
    const char* qlB = (const char*)g_ql + (size_t)b * NN * 128;
    const char* vhB = (const char*)g_vh + ((size_t)b * C_ * NN + mbase) * 2;
    const char* vlB = (const char*)g_vl + ((size_t)b * C_ * NN + mbase) * 2;

    cp_tile128(sb + P_AH, qhB + (size_t)n0 * 128, tid);
    cp_tile128(sb + P_AL, qlB + (size_t)n0 * 128, tid);
    CP_COMMIT();
    cp_tile64(sb + P_BH, qhB + (size_t)mbase * 128, tid);
    cp_tile64(sb + P_BL, qlB + (size_t)mbase * 128, tid);
    cp_v64(sb + P_VH, vhB, tid);
    cp_v64(sb + P_VL, vlB, tid);
    CP_COMMIT();

    int nrow0 = n0 + wid * 16 + (lane >> 2);
    float inv0 = 1.0f / g_sum[b * NN + nrow0];
    float inv1 = 1.0f / g_sum[b * NN + nrow0 + 8];
    float* betaRow0 = beta + ((size_t)b * NN + nrow0) * NN + mbase + (lane & 3) * 2;
    float* betaRow1 = betaRow0 + (size_t)8 * NN;

    float O[8][4];
#pragma unroll
    for (int q = 0; q < 8; q++) { O[q][0] = O[q][1] = O[q][2] = O[q][3] = 0.f; }

    float C[8][4];
    int kc = (lane >> 4) * 16;
    int rowB = lane & 15;

    for (int mt = 0; mt < 18; mt++) {
        int m0 = mt * 64;
        int cur = mt & 1;
        if (mt + 1 < 18) {
            int nxt = cur ^ 1;
            cp_tile64(sb + P_BH + nxt * 8192, qhB + (size_t)(mbase + m0 + 64) * 128, tid);
            cp_tile64(sb + P_BL + nxt * 8192, qlB + (size_t)(mbase + m0 + 64) * 128, tid);
            cp_v64(sb + P_VH + nxt * 8192, vhB + (size_t)(m0 + 64) * 2, tid);
            cp_v64(sb + P_VL + nxt * 8192, vlB + (size_t)(m0 + 64) * 2, tid);
            CP_COMMIT();
            CP_WAIT(1);
        } else {
            CP_WAIT(0);
        }
        __syncthreads();

        compute_S64(C, sb + P_AH, sb + P_AL,
                    sb + P_BH + cur * 8192, sb + P_BL + cur * 8192, lane, wid * 16);

        // exp + normalize + write beta
#pragma unroll
        for (int j = 0; j < 8; j++) {
            float e0 = __expf(fmaf(C[j][0], bg, mshift)) * inv0;
            float e1 = __expf(fmaf(C[j][1], bg, mshift)) * inv0;
            float e2 = __expf(fmaf(C[j][2], bg, mshift)) * inv1;
            float e3 = __expf(fmaf(C[j][3], bg, mshift)) * inv1;
            C[j][0] = e0; C[j][1] = e1; C[j][2] = e2; C[j][3] = e3;
            *reinterpret_cast<float2*>(betaRow0 + m0 + j * 8) = make_float2(e0, e1);
            *reinterpret_cast<float2*>(betaRow1 + m0 + j * 8) = make_float2(e2, e3);
        }

        // O += P * V^T
        uint32_t vH = sb + P_VH + cur * 8192;
        uint32_t vL = sb + P_VL + cur * 8192;
#pragma unroll
        for (int kk = 0; kk < 4; kk++) {
            uint32_t pH[4], pL[4];
            pH[0] = hipack(C[2 * kk][0],     C[2 * kk][1]);
            pH[1] = hipack(C[2 * kk][2],     C[2 * kk][3]);
            pH[2] = hipack(C[2 * kk + 1][0], C[2 * kk + 1][1]);
            pH[3] = hipack(C[2 * kk + 1][2], C[2 * kk + 1][3]);
            pL[0] = lopack(C[2 * kk][0],     C[2 * kk][1]);
            pL[1] = lopack(C[2 * kk][2],     C[2 * kk][3]);
            pL[2] = lopack(C[2 * kk + 1][0], C[2 * kk + 1][1]);
            pL[3] = lopack(C[2 * kk + 1][2], C[2 * kk + 1][3]);
            uint32_t vbase = (uint32_t)(kk * 32 + kc);
#pragma unroll
            for (int q = 0; q < 4; q++) {
                uint32_t boff = swz((uint32_t)((q * 16 + rowB) * 128) + vbase);
                uint32_t b0, b1, b2, b3;
                ldsm4(b0, b1, b2, b3, vH + boff);
                mma_bf16(O[2 * q],     pH, b0, b2);
                mma_bf16(O[2 * q + 1], pH, b1, b3);
                mma_bf16(O[2 * q],     pL, b0, b2);
                mma_bf16(O[2 * q + 1], pL, b1, b3);
                ldsm4(b0, b1, b2, b3, vL + boff);
                mma_bf16(O[2 * q],     pH, b0, b2);
                mma_bf16(O[2 * q + 1], pH, b1, b3);
            }
        }
        __syncthreads();
    }

    // accumulate O partial (2 contributing CTAs -> order-independent fp add)
    int nr0 = n0 + wid * 16 + (lane >> 2);
#pragma unroll
    for (int q = 0; q < 8; q++) {
        int c = q * 8 + (lane & 3) * 2;
        size_t base0 = ((size_t)b * C_ + c) * NN + nr0;
        atomicAdd(&g_o[base0],          O[q][0]);
        atomicAdd(&g_o[base0 + NN],     O[q][1]);
        atomicAdd(&g_o[base0 + 8],      O[q][2]);
        atomicAdd(&g_o[base0 + NN + 8], O[q][3]);
    }
}

// ---------------- combine: out = w0*g_o + w1*v ----------------
__global__ __launch_bounds__(256) void combine_kernel(float* __restrict__ out,
                                                      const float* __restrict__ v,
                                                      const float* __restrict__ sg0_p,
                                                      const float* __restrict__ sg1_p) {
    int i = blockIdx.x * blockDim.x + threadIdx.x;
    int total = B_ * C_ * NN / 4;
    if (i >= total) return;
    float eg0 = __expf(*sg0_p), eg1 = __expf(*sg1_p);
    float tot = eg0 + eg1;
    float w0 = eg0 / tot, w1 = eg1 / tot;
    float4 o = reinterpret_cast<const float4*>(g_o)[i];
    float4 vv = reinterpret_cast<const float4*>(v)[i];
    float4 r;
    r.x = w0 * o.x + w1 * vv.x;
    r.y = w0 * o.y + w1 * vv.y;
    r.z = w0 * o.z + w1 * vv.z;
    r.w = w0 * o.w + w1 * vv.w;
    reinterpret_cast<float4*>(out)[i] = r;
}

// ---------------- launch ----------------
extern "C" void kernel_launch(void* const* d_in, const int* in_sizes, int n_in,
                              void* d_out, int out_size) {
    const float* x     = (const float*)d_in[0];
    const float* v     = (const float*)d_in[1];
    const float* pos   = (const float*)d_in[2];
    const float* gamma = (const float*)d_in[3];
    const float* bg    = (const float*)d_in[4];
    const float* sg0   = (const float*)d_in[5];
    const float* sg1   = (const float*)d_in[6];

    float* out  = (float*)d_out;
    float* beta = out + (size_t)B_ * C_ * NN;

    cudaFuncSetAttribute(rowsum_kernel, cudaFuncAttributeMaxDynamicSharedMemorySize, A_SMEM);
    cudaFuncSetAttribute(attn_kernel,   cudaFuncAttributeMaxDynamicSharedMemorySize, P_SMEM);

    qsplit_kernel<<<(B_ * NN + 255) / 256, 256>>>(x, pos, gamma);
    vsplit_kernel<<<(B_ * C_ * NN / 2 + 255) / 256, 256>>>(v);

    dim3 grid(NT_N, 2, B_);
    rowsum_kernel<<<grid, 256, A_SMEM>>>(bg);
    attn_kernel<<<grid, 256, P_SMEM>>>(beta, bg);
    combine_kernel<<<(B_ * C_ * NN / 4 + 255) / 256, 256>>>(out, v, sg0, sg1);
}

// round 6
// speedup vs baseline: 2.6597x; 1.1144x over previous
#include <cuda_runtime.h>
#include <math.h>
#include <stdint.h>

#define B_   8
#define C_   64
#define NN   2304          // 48*48
#define NH   1152          // NN/2, m-half
#define NBLK 128           // n rows per CTA
#define NT_N 18

// ---------------- scratch ----------------
__device__ unsigned short g_qh[B_ * NN * C_];   // [b][n][c] bf16 hi
__device__ unsigned short g_ql[B_ * NN * C_];   // residual
__device__ unsigned short g_vh[B_ * C_ * NN];   // [b][c][m]
__device__ unsigned short g_vl[B_ * C_ * NN];
__device__ float          g_sum[B_ * NN];       // rowsum (atomic)
__device__ float          g_o[B_ * C_ * NN];    // O accumulation (atomic)

// ---------------- helpers ----------------
static __device__ __forceinline__ uint32_t smem_u32(const void* p) {
    uint32_t a;
    asm("{ .reg .u64 t; cvta.to.shared.u64 t, %1; cvt.u32.u64 %0, t; }" : "=r"(a) : "l"(p));
    return a;
}
static __device__ __forceinline__ uint32_t swz(uint32_t o) { return o ^ ((o >> 3) & 0x70u); }

static __device__ __forceinline__ void ldsm4(uint32_t& r0, uint32_t& r1,
                                             uint32_t& r2, uint32_t& r3, uint32_t a) {
    asm volatile("ldmatrix.sync.aligned.m8n8.x4.shared.b16 {%0,%1,%2,%3}, [%4];"
                 : "=r"(r0), "=r"(r1), "=r"(r2), "=r"(r3) : "r"(a));
}
static __device__ __forceinline__ void mma_bf16(float (&d)[4], const uint32_t (&a)[4],
                                                uint32_t b0, uint32_t b1) {
    asm volatile(
        "mma.sync.aligned.m16n8k16.row.col.f32.bf16.bf16.f32 "
        "{%0,%1,%2,%3}, {%4,%5,%6,%7}, {%8,%9}, {%0,%1,%2,%3};"
        : "+f"(d[0]), "+f"(d[1]), "+f"(d[2]), "+f"(d[3])
        : "r"(a[0]), "r"(a[1]), "r"(a[2]), "r"(a[3]), "r"(b0), "r"(b1));
}
static __device__ __forceinline__ uint32_t hipack(float x, float y) {
    return __byte_perm(__float_as_uint(x), __float_as_uint(y), 0x7632);
}
static __device__ __forceinline__ uint32_t lopack(float x, float y) {
    float rx = x - __uint_as_float(__float_as_uint(x) & 0xFFFF0000u);
    float ry = y - __uint_as_float(__float_as_uint(y) & 0xFFFF0000u);
    uint32_t r;
    asm("cvt.rn.bf16x2.f32 %0, %1, %2;" : "=r"(r) : "f"(ry), "f"(rx));
    return r;
}
static __device__ __forceinline__ void stg_cs2(float* p, float x, float y) {
    asm volatile("st.global.cs.v2.f32 [%0], {%1, %2};" :: "l"(p), "f"(x), "f"(y) : "memory");
}

// ---------------- cp.async ----------------
#define CP16(dst, src) \
    asm volatile("cp.async.cg.shared.global [%0], [%1], 16;" :: "r"(dst), "l"(src))
#define CP_COMMIT()  asm volatile("cp.async.commit_group;" ::: "memory")
#define CP_WAIT(n)   asm volatile("cp.async.wait_group %0;" :: "n"(n) : "memory")

// 128 rows x 128B contiguous -> swizzled smem
static __device__ __forceinline__ void cp_tile128(uint32_t sdst, const char* g, int tid) {
#pragma unroll
    for (int k = 0; k < 4; k++) {
        int i = tid + k * 256;
        CP16(sdst + swz((uint32_t)i * 16), g + (size_t)i * 16);
    }
}
// 64 rows x 128B contiguous -> swizzled smem
static __device__ __forceinline__ void cp_tile64(uint32_t sdst, const char* g, int tid) {
#pragma unroll
    for (int k = 0; k < 2; k++) {
        int i = tid + k * 256;
        CP16(sdst + swz((uint32_t)i * 16), g + (size_t)i * 16);
    }
}
// V tile: 64 rows (c) x 128B (64 m bf16), row stride NN*2
static __device__ __forceinline__ void cp_v64(uint32_t sdst, const char* g, int tid) {
#pragma unroll
    for (int k = 0; k < 2; k++) {
        int i = tid + k * 256;
        int c = i >> 3, j = i & 7;
        CP16(sdst + swz((uint32_t)(c * 128 + j * 16)), g + (size_t)c * (NN * 2) + j * 16);
    }
}

// ---------------- phase 1a: q split (+ zero g_sum) ----------------
__global__ __launch_bounds__(256) void qsplit_kernel(const float* __restrict__ x,
                                                     const float* __restrict__ pos,
                                                     const float* __restrict__ gamma_p) {
    int idx = blockIdx.x * blockDim.x + threadIdx.x;
    if (idx >= B_ * NN) return;
    g_sum[idx] = 0.f;
    int b = idx / NN, n = idx - b * NN;
    float gamma = *gamma_p;
    const float* xb = x   + (size_t)b * C_ * NN + n;
    const float* pb = pos + (size_t)b * C_ * NN + n;
    float q[C_]; float s = 0.f;
#pragma unroll
    for (int c = 0; c < C_; c++) {
        float v = xb[(size_t)c * NN] + gamma * pb[(size_t)c * NN];
        q[c] = v; s += v * v;
    }
    float inv = 1.0f / sqrtf(s + 1e-6f);
    uint32_t hp[32], lp[32];
#pragma unroll
    for (int i = 0; i < 32; i++) {
        float a = q[2 * i] * inv, bv = q[2 * i + 1] * inv;
        hp[i] = hipack(a, bv);
        lp[i] = lopack(a, bv);
    }
    uint4* ph = reinterpret_cast<uint4*>(reinterpret_cast<uint32_t*>(g_qh) + (size_t)idx * 32);
    uint4* pl = reinterpret_cast<uint4*>(reinterpret_cast<uint32_t*>(g_ql) + (size_t)idx * 32);
#pragma unroll
    for (int j = 0; j < 8; j++) {
        ph[j] = make_uint4(hp[4 * j], hp[4 * j + 1], hp[4 * j + 2], hp[4 * j + 3]);
        pl[j] = make_uint4(lp[4 * j], lp[4 * j + 1], lp[4 * j + 2], lp[4 * j + 3]);
    }
}

// ---------------- phase 1b: v split (+ zero g_o) ----------------
__global__ __launch_bounds__(256) void vsplit_kernel(const float* __restrict__ v) {
    int i = blockIdx.x * blockDim.x + threadIdx.x;
    int total = B_ * C_ * NN / 2;
    if (i >= total) return;
    float2 p = reinterpret_cast<const float2*>(v)[i];
    reinterpret_cast<uint32_t*>(g_vh)[i] = hipack(p.x, p.y);
    reinterpret_cast<uint32_t*>(g_vl)[i] = lopack(p.x, p.y);
    reinterpret_cast<float2*>(g_o)[i] = make_float2(0.f, 0.f);
}

// ---------------- S tile, MT=128: per-warp 16x128 ----------------
static __device__ __forceinline__ void compute_S128(float (&C)[16][4],
                                                    uint32_t sAH, uint32_t sAL,
                                                    uint32_t sBH, uint32_t sBL,
                                                    int lane, int rowA0) {
#pragma unroll
    for (int j = 0; j < 16; j++) { C[j][0] = C[j][1] = C[j][2] = C[j][3] = 0.f; }
    int rowA = rowA0 + (lane & 15);
    int kc = (lane >> 4) * 16;
    int rowB = lane & 15;
#pragma unroll
    for (int ks = 0; ks < 4; ks++) {
        uint32_t aoff = swz((uint32_t)(rowA * 128 + ks * 32 + kc));
        uint32_t aH[4], aL[4];
        ldsm4(aH[0], aH[1], aH[2], aH[3], sAH + aoff);
        ldsm4(aL[0], aL[1], aL[2], aL[3], sAL + aoff);
#pragma unroll
        for (int p = 0; p < 8; p++) {
            uint32_t boff = swz((uint32_t)((p * 16 + rowB) * 128 + ks * 32 + kc));
            uint32_t b0, b1, b2, b3;
            ldsm4(b0, b1, b2, b3, sBH + boff);
            mma_bf16(C[2 * p],     aH, b0, b2);
            mma_bf16(C[2 * p + 1], aH, b1, b3);
            mma_bf16(C[2 * p],     aL, b0, b2);
            mma_bf16(C[2 * p + 1], aL, b1, b3);
            ldsm4(b0, b1, b2, b3, sBL + boff);
            mma_bf16(C[2 * p],     aH, b0, b2);
            mma_bf16(C[2 * p + 1], aH, b1, b3);
        }
    }
}

// ---------------- S tile, MT=64 (attn): per-warp 16x64 ----------------
static __device__ __forceinline__ void compute_S64(float (&C)[8][4],
                                                   uint32_t sAH, uint32_t sAL,
                                                   uint32_t sBH, uint32_t sBL,
                                                   int lane, int rowA0) {
#pragma unroll
    for (int j = 0; j < 8; j++) { C[j][0] = C[j][1] = C[j][2] = C[j][3] = 0.f; }
    int rowA = rowA0 + (lane & 15);
    int kc = (lane >> 4) * 16;
    int rowB = lane & 15;
#pragma unroll
    for (int ks = 0; ks < 4; ks++) {
        uint32_t aoff = swz((uint32_t)(rowA * 128 + ks * 32 + kc));
        uint32_t aH[4], aL[4];
        ldsm4(aH[0], aH[1], aH[2], aH[3], sAH + aoff);
        ldsm4(aL[0], aL[1], aL[2], aL[3], sAL + aoff);
#pragma unroll
        for (int p = 0; p < 4; p++) {
            uint32_t boff = swz((uint32_t)((p * 16 + rowB) * 128 + ks * 32 + kc));
            uint32_t b0, b1, b2, b3;
            ldsm4(b0, b1, b2, b3, sBH + boff);
            mma_bf16(C[2 * p],     aH, b0, b2);
            mma_bf16(C[2 * p + 1], aH, b1, b3);
            mma_bf16(C[2 * p],     aL, b0, b2);
            mma_bf16(C[2 * p + 1], aL, b1, b3);
            ldsm4(b0, b1, b2, b3, sBL + boff);
            mma_bf16(C[2 * p],     aH, b0, b2);
            mma_bf16(C[2 * p + 1], aH, b1, b3);
        }
    }
}

// ---------------- pass A: SYMMETRIC rowsums ----------------
// grid (4, 9, 8): stride-q over the balanced chain of rows (p, 17-p), 19 tiles.
// For off-diagonal tile (I,J): row-sums for block I (register accum) and
// column-sums for block J (butterfly + atomicAdd) via E symmetry.
#define A_AH 0
#define A_AL 16384
#define A_BH 32768          // [2] +16384*s
#define A_BL 65536          // [2]
#define A_SMEM 98304

__global__ __launch_bounds__(256, 2) void rowsum_kernel(const float* __restrict__ bg_p) {
    extern __shared__ char smem[];
    uint32_t sb = smem_u32(smem);
    int tid = threadIdx.x, wid = tid >> 5, lane = tid & 31;
    int qstr = blockIdx.x, p = blockIdx.y, b = blockIdx.z;
    float bg = *bg_p, mshift = -fabsf(bg);

    const char* qhB = (const char*)g_qh + (size_t)b * NN * 128;
    const char* qlB = (const char*)g_ql + (size_t)b * NN * 128;
    float* sumB = g_sum + b * NN;

    float C[16][4];

#pragma unroll 1
    for (int phase = 0; phase < 2; phase++) {
        int I, jfirst, jlast;
        if (phase == 0) {
            I = p; jfirst = qstr; jlast = p;
        } else {
            I = 17 - p;
            int d = p + 1 - qstr;
            int k = (d > 0) ? ((d + 3) >> 2) : 0;
            jfirst = qstr + 4 * k - p - 1;
            jlast = 17 - p;
        }
        if (jfirst > jlast) continue;

        // load A(I) + first B
        cp_tile128(sb + A_AH, qhB + (size_t)I * 16384, tid);
        cp_tile128(sb + A_AL, qlB + (size_t)I * 16384, tid);
        CP_COMMIT();
        cp_tile128(sb + A_BH, qhB + (size_t)jfirst * 16384, tid);
        cp_tile128(sb + A_BL, qlB + (size_t)jfirst * 16384, tid);
        CP_COMMIT();

        float r0 = 0.f, r1 = 0.f;
        int buf = 0;
#pragma unroll 1
        for (int J = jfirst; J <= jlast; J += 4, buf ^= 1) {
            if (J + 4 <= jlast) {
                int nxt = buf ^ 1;
                cp_tile128(sb + A_BH + nxt * 16384, qhB + (size_t)(J + 4) * 16384, tid);
                cp_tile128(sb + A_BL + nxt * 16384, qlB + (size_t)(J + 4) * 16384, tid);
                CP_COMMIT();
                CP_WAIT(1);
            } else {
                CP_WAIT(0);
            }
            __syncthreads();
            compute_S128(C, sb + A_AH, sb + A_AL,
                         sb + A_BH + buf * 16384, sb + A_BL + buf * 16384, lane, wid * 16);
            __syncthreads();   // B buffer free for next prefetch

            // exp in place
#pragma unroll
            for (int j = 0; j < 16; j++) {
                C[j][0] = __expf(fmaf(C[j][0], bg, mshift));
                C[j][1] = __expf(fmaf(C[j][1], bg, mshift));
                C[j][2] = __expf(fmaf(C[j][2], bg, mshift));
                C[j][3] = __expf(fmaf(C[j][3], bg, mshift));
            }
            // row-sum accumulate (block I rows)
#pragma unroll
            for (int j = 0; j < 16; j++) {
                r0 += C[j][0] + C[j][1];
                r1 += C[j][2] + C[j][3];
            }
            // column-sums -> block J rows (symmetry), skip diagonal
            if (I != J) {
#pragma unroll
                for (int j = 0; j < 16; j++) {
                    float v0 = C[j][0] + C[j][2];
                    float v1 = C[j][1] + C[j][3];
                    v0 += __shfl_xor_sync(0xffffffffu, v0, 4);
                    v0 += __shfl_xor_sync(0xffffffffu, v0, 8);
                    v0 += __shfl_xor_sync(0xffffffffu, v0, 16);
                    v1 += __shfl_xor_sync(0xffffffffu, v1, 4);
                    v1 += __shfl_xor_sync(0xffffffffu, v1, 8);
                    v1 += __shfl_xor_sync(0xffffffffu, v1, 16);
                    if (lane < 4) {
                        int m = J * 128 + j * 8 + lane * 2;
                        atomicAdd(&sumB[m], v0);
                        atomicAdd(&sumB[m + 1], v1);
                    }
                }
            }
        }
        // phase-end row-sum atomics
        r0 += __shfl_xor_sync(0xffffffffu, r0, 1);
        r0 += __shfl_xor_sync(0xffffffffu, r0, 2);
        r1 += __shfl_xor_sync(0xffffffffu, r1, 1);
        r1 += __shfl_xor_sync(0xffffffffu, r1, 2);
        if ((lane & 3) == 0) {
            int n = I * 128 + wid * 16 + (lane >> 2);
            atomicAdd(&sumB[n], r0);
            atomicAdd(&sumB[n + 8], r1);
        }
    }
}

// ---------------- pass B: beta + O, grid (18, 2, 8), MT=64, 18 tiles ----------------
#define P_AH 0
#define P_AL 16384
#define P_BH 32768          // [2] +8192*s
#define P_BL 49152          // [2]
#define P_VH 65536          // [2]
#define P_VL 81920          // [2]
#define P_SMEM 98304

__global__ __launch_bounds__(256, 2) void attn_kernel(float* __restrict__ beta,
                                                      const float* __restrict__ bg_p) {
    extern __shared__ char smem[];
    uint32_t sb = smem_u32(smem);
    int tid = threadIdx.x, wid = tid >> 5, lane = tid & 31;
    int b = blockIdx.z, n0 = blockIdx.x * NBLK, mbase = blockIdx.y * NH;
    float bg = *bg_p, mshift = -fabsf(bg);

    const char* qhB = (const char*)g_qh + (size_t)b * NN * 128;
    const char* qlB = (const char*)g_ql + (size_t)b * NN * 128;
    const char* vhB = (const char*)g_vh + ((size_t)b * C_ * NN + mbase) * 2;
    const char* vlB = (const char*)g_vl + ((size_t)b * C_ * NN + mbase) * 2;

    cp_tile128(sb + P_AH, qhB + (size_t)n0 * 128, tid);
    cp_tile128(sb + P_AL, qlB + (size_t)n0 * 128, tid);
    CP_COMMIT();
    cp_tile64(sb + P_BH, qhB + (size_t)mbase * 128, tid);
    cp_tile64(sb + P_BL, qlB + (size_t)mbase * 128, tid);
    cp_v64(sb + P_VH, vhB, tid);
    cp_v64(sb + P_VL, vlB, tid);
    CP_COMMIT();

    int nrow0 = n0 + wid * 16 + (lane >> 2);
    float inv0 = 1.0f / g_sum[b * NN + nrow0];
    float inv1 = 1.0f / g_sum[b * NN + nrow0 + 8];
    float* betaRow0 = beta + ((size_t)b * NN + nrow0) * NN + mbase + (lane & 3) * 2;
    float* betaRow1 = betaRow0 + (size_t)8 * NN;

    float O[8][4];
#pragma unroll
    for (int q = 0; q < 8; q++) { O[q][0] = O[q][1] = O[q][2] = O[q][3] = 0.f; }

    float C[8][4];
    int kc = (lane >> 4) * 16;
    int rowB = lane & 15;

    for (int mt = 0; mt < 18; mt++) {
        int m0 = mt * 64;
        int cur = mt & 1;
        if (mt + 1 < 18) {
            int nxt = cur ^ 1;
            cp_tile64(sb + P_BH + nxt * 8192, qhB + (size_t)(mbase + m0 + 64) * 128, tid);
            cp_tile64(sb + P_BL + nxt * 8192, qlB + (size_t)(mbase + m0 + 64) * 128, tid);
            cp_v64(sb + P_VH + nxt * 8192, vhB + (size_t)(m0 + 64) * 2, tid);
            cp_v64(sb + P_VL + nxt * 8192, vlB + (size_t)(m0 + 64) * 2, tid);
            CP_COMMIT();
            CP_WAIT(1);
        } else {
            CP_WAIT(0);
        }
        __syncthreads();

        compute_S64(C, sb + P_AH, sb + P_AL,
                    sb + P_BH + cur * 8192, sb + P_BL + cur * 8192, lane, wid * 16);

        // exp + normalize + write beta (streaming stores)
#pragma unroll
        for (int j = 0; j < 8; j++) {
            float e0 = __expf(fmaf(C[j][0], bg, mshift)) * inv0;
            float e1 = __expf(fmaf(C[j][1], bg, mshift)) * inv0;
            float e2 = __expf(fmaf(C[j][2], bg, mshift)) * inv1;
            float e3 = __expf(fmaf(C[j][3], bg, mshift)) * inv1;
            C[j][0] = e0; C[j][1] = e1; C[j][2] = e2; C[j][3] = e3;
            stg_cs2(betaRow0 + m0 + j * 8, e0, e1);
            stg_cs2(betaRow1 + m0 + j * 8, e2, e3);
        }

        // O += P * V^T
        uint32_t vH = sb + P_VH + cur * 8192;
        uint32_t vL = sb + P_VL + cur * 8192;
#pragma unroll
        for (int kk = 0; kk < 4; kk++) {
            uint32_t pH[4], pL[4];
            pH[0] = hipack(C[2 * kk][0],     C[2 * kk][1]);
            pH[1] = hipack(C[2 * kk][2],     C[2 * kk][3]);
            pH[2] = hipack(C[2 * kk + 1][0], C[2 * kk + 1][1]);
            pH[3] = hipack(C[2 * kk + 1][2], C[2 * kk + 1][3]);
            pL[0] = lopack(C[2 * kk][0],     C[2 * kk][1]);
            pL[1] = lopack(C[2 * kk][2],     C[2 * kk][3]);
            pL[2] = lopack(C[2 * kk + 1][0], C[2 * kk + 1][1]);
            pL[3] = lopack(C[2 * kk + 1][2], C[2 * kk + 1][3]);
            uint32_t vbase = (uint32_t)(kk * 32 + kc);
#pragma unroll
            for (int q = 0; q < 4; q++) {
                uint32_t boff = swz((uint32_t)((q * 16 + rowB) * 128) + vbase);
                uint32_t b0, b1, b2, b3;
                ldsm4(b0, b1, b2, b3, vH + boff);
                mma_bf16(O[2 * q],     pH, b0, b2);
                mma_bf16(O[2 * q + 1], pH, b1, b3);
                mma_bf16(O[2 * q],     pL, b0, b2);
                mma_bf16(O[2 * q + 1], pL, b1, b3);
                ldsm4(b0, b1, b2, b3, vL + boff);
                mma_bf16(O[2 * q],     pH, b0, b2);
                mma_bf16(O[2 * q + 1], pH, b1, b3);
            }
        }
        __syncthreads();
    }

    // accumulate O partial (2 contributing CTAs -> order-independent fp add)
    int nr0 = n0 + wid * 16 + (lane >> 2);
#pragma unroll
    for (int q = 0; q < 8; q++) {
        int c = q * 8 + (lane & 3) * 2;
        size_t base0 = ((size_t)b * C_ + c) * NN + nr0;
        atomicAdd(&g_o[base0],          O[q][0]);
        atomicAdd(&g_o[base0 + NN],     O[q][1]);
        atomicAdd(&g_o[base0 + 8],      O[q][2]);
        atomicAdd(&g_o[base0 + NN + 8], O[q][3]);
    }
}

// ---------------- combine: out = w0*g_o + w1*v ----------------
__global__ __launch_bounds__(256) void combine_kernel(float* __restrict__ out,
                                                      const float* __restrict__ v,
                                                      const float* __restrict__ sg0_p,
                                                      const float* __restrict__ sg1_p) {
    int i = blockIdx.x * blockDim.x + threadIdx.x;
    int total = B_ * C_ * NN / 4;
    if (i >= total) return;
    float eg0 = __expf(*sg0_p), eg1 = __expf(*sg1_p);
    float tot = eg0 + eg1;
    float w0 = eg0 / tot, w1 = eg1 / tot;
    float4 o = reinterpret_cast<const float4*>(g_o)[i];
    float4 vv = reinterpret_cast<const float4*>(v)[i];
    float4 r;
    r.x = w0 * o.x + w1 * vv.x;
    r.y = w0 * o.y + w1 * vv.y;
    r.z = w0 * o.z + w1 * vv.z;
    r.w = w0 * o.w + w1 * vv.w;
    reinterpret_cast<float4*>(out)[i] = r;
}

// ---------------- launch ----------------
extern "C" void kernel_launch(void* const* d_in, const int* in_sizes, int n_in,
                              void* d_out, int out_size) {
    const float* x     = (const float*)d_in[0];
    const float* v     = (const float*)d_in[1];
    const float* pos   = (const float*)d_in[2];
    const float* gamma = (const float*)d_in[3];
    const float* bg    = (const float*)d_in[4];
    const float* sg0   = (const float*)d_in[5];
    const float* sg1   = (const float*)d_in[6];

    float* out  = (float*)d_out;
    float* beta = out + (size_t)B_ * C_ * NN;

    cudaFuncSetAttribute(rowsum_kernel, cudaFuncAttributeMaxDynamicSharedMemorySize, A_SMEM);
    cudaFuncSetAttribute(attn_kernel,   cudaFuncAttributeMaxDynamicSharedMemorySize, P_SMEM);

    qsplit_kernel<<<(B_ * NN + 255) / 256, 256>>>(x, pos, gamma);
    vsplit_kernel<<<(B_ * C_ * NN / 2 + 255) / 256, 256>>>(v);

    dim3 gridA(4, 9, B_);
    rowsum_kernel<<<gridA, 256, A_SMEM>>>(bg);
    dim3 gridB(NT_N, 2, B_);
    attn_kernel<<<gridB, 256, P_SMEM>>>(beta, bg);
    combine_kernel<<<(B_ * C_ * NN / 4 + 255) / 256, 256>>>(out, v, sg0, sg1);
}